// round 6
// baseline (speedup 1.0000x reference)
#include <cuda_runtime.h>
#include <cuda_bf16.h>
#include <math.h>
#include <stdint.h>

#define DDIM 256
#define PDIM 64
#define MTILE 128
#define NTHREADS 512

// row pitches (bytes), all ≡16 mod 128 -> conflict-free ldmatrix row sets
#define CPF 528     // C splits [64 p][256 k] bf16 + pad
#define QP  272     // Q splits [128 m][128 k] bf16 + pad (per K-half)
#define SP  272     // sims [128 m][64 p] f32 + pad
#define WP  144     // W splits [128 m][64 p] bf16 + pad

// ---- smem byte offsets ----
#define CH_O 0            // C hi  (live through GEMM2)
#define CM_O 33792        // C mid (live through GEMM2; == split2-lo of C)
#define CL_O 67584        // C lo
#define QH_O 101376       // Q hi (per half)
#define QM_O 136192
#define QL_O 171008
#define S0_O 101376       // sims partial group0 (aliases QH, dead after GEMM1)
#define S1_O 136192       // sims partial group1 (aliases QM)
#define WH_O 171008       // W hi (aliases QL)
#define WL_O 189440
#define QSS_O 207872      // 128 f32
#define CQQ_O 208384      // 64 f32
#define CISM_O 208640     // 64 f32
#define NEGM_O 208896     // 64 f32
#define SMEM_BYTES 209152

__device__ __forceinline__ uint32_t smem_u32(const void* p) {
    uint32_t a;
    asm("{ .reg .u64 t; cvta.to.shared.u64 t, %1; cvt.u32.u64 %0, t; }" : "=r"(a) : "l"(p));
    return a;
}
__device__ __forceinline__ void ldsm4(uint32_t addr, uint32_t& r0, uint32_t& r1,
                                      uint32_t& r2, uint32_t& r3) {
    asm volatile("ldmatrix.sync.aligned.m8n8.x4.shared.b16 {%0,%1,%2,%3}, [%4];"
                 : "=r"(r0), "=r"(r1), "=r"(r2), "=r"(r3) : "r"(addr));
}
__device__ __forceinline__ void ldsm4t(uint32_t addr, uint32_t& r0, uint32_t& r1,
                                       uint32_t& r2, uint32_t& r3) {
    asm volatile("ldmatrix.sync.aligned.m8n8.x4.trans.shared.b16 {%0,%1,%2,%3}, [%4];"
                 : "=r"(r0), "=r"(r1), "=r"(r2), "=r"(r3) : "r"(addr));
}
__device__ __forceinline__ void mma16816(float* d, uint32_t a0, uint32_t a1, uint32_t a2,
                                         uint32_t a3, uint32_t b0, uint32_t b1) {
    asm volatile("mma.sync.aligned.m16n8k16.row.col.f32.bf16.bf16.f32 "
                 "{%0,%1,%2,%3}, {%4,%5,%6,%7}, {%8,%9}, {%0,%1,%2,%3};"
                 : "+f"(d[0]), "+f"(d[1]), "+f"(d[2]), "+f"(d[3])
                 : "r"(a0), "r"(a1), "r"(a2), "r"(a3), "r"(b0), "r"(b1));
}

__device__ __forceinline__ void split3(float x, unsigned short& h, unsigned short& m,
                                       unsigned short& l) {
    __nv_bfloat16 bh = __float2bfloat16(x);
    float r = x - __bfloat162float(bh);
    __nv_bfloat16 bm = __float2bfloat16(r);
    __nv_bfloat16 bl = __float2bfloat16(r - __bfloat162float(bm));
    h = __bfloat16_as_ushort(bh);
    m = __bfloat16_as_ushort(bm);
    l = __bfloat16_as_ushort(bl);
}
__device__ __forceinline__ void split2(float x, unsigned short& h, unsigned short& l) {
    __nv_bfloat16 bh = __float2bfloat16(x);
    __nv_bfloat16 bl = __float2bfloat16(x - __bfloat162float(bh));
    h = __bfloat16_as_ushort(bh);
    l = __bfloat16_as_ushort(bl);
}
__device__ __forceinline__ uint32_t pk(unsigned short a, unsigned short b) {
    return (uint32_t)a | ((uint32_t)b << 16);
}
__device__ __forceinline__ void conv8(const float4* src, char* dh, char* dm, char* dl,
                                      uint32_t off, float& acc) {
    float4 a = src[0], b = src[1];
    float xs[8] = {a.x, a.y, a.z, a.w, b.x, b.y, b.z, b.w};
    unsigned short h[8], m[8], l[8];
    #pragma unroll
    for (int i = 0; i < 8; ++i) {
        acc = fmaf(xs[i], xs[i], acc);
        split3(xs[i], h[i], m[i], l[i]);
    }
    *(uint4*)(dh + off) = make_uint4(pk(h[0], h[1]), pk(h[2], h[3]), pk(h[4], h[5]), pk(h[6], h[7]));
    *(uint4*)(dm + off) = make_uint4(pk(m[0], m[1]), pk(m[2], m[3]), pk(m[4], m[5]), pk(m[6], m[7]));
    *(uint4*)(dl + off) = make_uint4(pk(l[0], l[1]), pk(l[2], l[3]), pk(l[4], l[5]), pk(l[6], l[7]));
}

// GEMM1 half: warp computes 32x32 tile over 128-k half for 3 split passes
__device__ __forceinline__ void gemm1_half(uint32_t smb, int g, int mrow, int ncol,
                                           int lane, int kc, float acc[8][4]) {
    const uint32_t qofs[6] = {QH_O, QH_O, QM_O, QH_O, QL_O, QM_O};
    const uint32_t cofs[6] = {CH_O, CM_O, CH_O, CL_O, CH_O, CM_O};
    const uint32_t lrow = (uint32_t)(lane & 15);
    const uint32_t lk = (uint32_t)((lane >> 4) * 16);
    #pragma unroll 1
    for (int ps = 0; ps < 3; ++ps) {
        uint32_t ab = smb + qofs[g * 3 + ps] + (mrow + lrow) * QP + lk;
        uint32_t bb = smb + cofs[g * 3 + ps] + (ncol + lrow) * CPF + kc * 256 + lk;
        #pragma unroll
        for (int ks = 0; ks < 8; ++ks) {
            uint32_t a0, a1, a2, a3, a4, a5, a6, a7, e0, e1, e2, e3, f0, f1, f2, f3;
            ldsm4(ab + ks * 32, a0, a1, a2, a3);
            ldsm4(ab + 16 * QP + ks * 32, a4, a5, a6, a7);
            ldsm4(bb + ks * 32, e0, e1, e2, e3);
            ldsm4(bb + 16 * CPF + ks * 32, f0, f1, f2, f3);
            mma16816(acc[0], a0, a1, a2, a3, e0, e2);
            mma16816(acc[1], a0, a1, a2, a3, e1, e3);
            mma16816(acc[2], a0, a1, a2, a3, f0, f2);
            mma16816(acc[3], a0, a1, a2, a3, f1, f3);
            mma16816(acc[4], a4, a5, a6, a7, e0, e2);
            mma16816(acc[5], a4, a5, a6, a7, e1, e3);
            mma16816(acc[6], a4, a5, a6, a7, f0, f2);
            mma16816(acc[7], a4, a5, a6, a7, f1, f3);
        }
    }
}

__global__ void __launch_bounds__(NTHREADS, 1)
centroid_hmma2_kernel(const float* __restrict__ gq,
                      const float* __restrict__ gc,
                      const int* __restrict__ gmask,
                      float* __restrict__ gctx,
                      float* __restrict__ gw,
                      float* __restrict__ ghard)
{
    extern __shared__ char sm[];
    const uint32_t smb = smem_u32(sm);
    const int t = threadIdx.x;
    const int wid = t >> 5, lane = t & 31;
    const int mbase = blockIdx.x * MTILE;

    float* qssf = (float*)(sm + QSS_O);
    float* cqqf = (float*)(sm + CQQ_O);
    float* cism = (float*)(sm + CISM_O);
    float* negm = (float*)(sm + NEGM_O);

    // GEMM1 warp mapping: group g does 3 of the 6 split passes; 4M x 2N grid of 32x32
    const int g = wid >> 3;
    const int mrow = ((wid >> 1) & 3) * 32;
    const int ncol = (wid & 1) * 32;

    // ---- convert C (full K=256) into 3 splits ----
    const int crow = t >> 3, cseg = t & 7;
    float cacc = 0.f;
    {
        const float4* src = (const float4*)(gc + (size_t)crow * DDIM + cseg * 32);
        uint32_t base = (uint32_t)(crow * CPF + cseg * 64);
        #pragma unroll
        for (int j = 0; j < 4; ++j)
            conv8(src + 2 * j, sm + CH_O, sm + CM_O, sm + CL_O, base + j * 16, cacc);
        cacc += __shfl_xor_sync(0xffffffffu, cacc, 1);
        cacc += __shfl_xor_sync(0xffffffffu, cacc, 2);
        cacc += __shfl_xor_sync(0xffffffffu, cacc, 4);
        if ((t & 7) == 0) cqqf[crow] = cacc;
    }
    // ---- convert Q half 0 ----
    const int qrow = t >> 2, qseg = t & 3;
    float qacc = 0.f;
    {
        const float4* src = (const float4*)(gq + (size_t)(mbase + qrow) * DDIM + qseg * 32);
        uint32_t base = (uint32_t)(qrow * QP + qseg * 64);
        #pragma unroll
        for (int j = 0; j < 4; ++j)
            conv8(src + 2 * j, sm + QH_O, sm + QM_O, sm + QL_O, base + j * 16, qacc);
    }
    __syncthreads();
    if (t < 64) {
        int mk = gmask[t];
        cism[t] = mk ? rsqrtf(fmaxf(cqqf[t], 1e-24f)) : 0.f;
        negm[t] = mk ? 0.f : -1e9f;
    }

    float acc[8][4];
    #pragma unroll
    for (int i = 0; i < 8; ++i)
        #pragma unroll
        for (int j = 0; j < 4; ++j) acc[i][j] = 0.f;

    // ---- GEMM1 half 0 ----
    gemm1_half(smb, g, mrow, ncol, lane, 0, acc);
    __syncthreads();

    // ---- convert Q half 1 ----
    {
        const float4* src = (const float4*)(gq + (size_t)(mbase + qrow) * DDIM + 128 + qseg * 32);
        uint32_t base = (uint32_t)(qrow * QP + qseg * 64);
        #pragma unroll
        for (int j = 0; j < 4; ++j)
            conv8(src + 2 * j, sm + QH_O, sm + QM_O, sm + QL_O, base + j * 16, qacc);
        qacc += __shfl_xor_sync(0xffffffffu, qacc, 1);
        qacc += __shfl_xor_sync(0xffffffffu, qacc, 2);
        if ((t & 3) == 0) qssf[qrow] = qacc;
    }
    __syncthreads();

    // ---- GEMM1 half 1 ----
    gemm1_half(smb, g, mrow, ncol, lane, 1, acc);
    __syncthreads();   // all Q reads done; sims buffers (alias QH/QM) writable

    // ---- store partial sims (per group buffer) ----
    {
        char* sbase = sm + (g ? S1_O : S0_O);
        const int r0 = mrow + (lane >> 2);
        const int cb = ncol + (lane & 3) * 2;
        #pragma unroll
        for (int mf = 0; mf < 2; ++mf)
            #pragma unroll
            for (int nf = 0; nf < 4; ++nf) {
                float* a = acc[mf * 4 + nf];
                *(float2*)(sbase + (r0 + mf * 16) * SP + (cb + nf * 8) * 4) = make_float2(a[0], a[1]);
                *(float2*)(sbase + (r0 + mf * 16 + 8) * SP + (cb + nf * 8) * 4) = make_float2(a[2], a[3]);
            }
    }
    __syncthreads();

    // ---- softmax/argmax + W 2-split (t < 128; one row per thread) ----
    if (t < 128) {
        const int m = t;
        const float qr = rsqrtf(fmaxf(qssf[m], 1e-24f));
        const float4* s0 = (const float4*)(sm + S0_O + m * SP);
        const float4* s1 = (const float4*)(sm + S1_O + m * SP);
        float s[64];
        float mx = -INFINITY;
        int mi = PDIM;
        #pragma unroll
        for (int gg = 0; gg < 16; ++gg) {
            float4 v = s0[gg], u = s1[gg];
            float vv[4] = {v.x + u.x, v.y + u.y, v.z + u.z, v.w + u.w};
            #pragma unroll
            for (int i = 0; i < 4; ++i) {
                int p = gg * 4 + i;
                float val = fmaf(vv[i] * qr, cism[p], negm[p]);
                s[p] = val;
                if (val > mx) { mx = val; mi = p; }   // strict >: first index wins
            }
        }
        float ssum = 0.f;
        #pragma unroll
        for (int p = 0; p < 64; ++p) {
            float e = expf(s[p] - mx);
            s[p] = e;
            ssum += e;
        }
        const float inv = 1.0f / ssum;
        float4* gwp = (float4*)(gw + (size_t)(mbase + m) * PDIM);
        char* wh = sm + WH_O + m * WP;
        char* wl = sm + WL_O + m * WP;
        #pragma unroll
        for (int gg = 0; gg < 16; ++gg) {
            float w0 = s[4 * gg + 0] * inv, w1 = s[4 * gg + 1] * inv;
            float w2 = s[4 * gg + 2] * inv, w3 = s[4 * gg + 3] * inv;
            gwp[gg] = make_float4(w0, w1, w2, w3);
            unsigned short h0, l0, h1, l1, h2, l2, h3, l3;
            split2(w0, h0, l0); split2(w1, h1, l1);
            split2(w2, h2, l2); split2(w3, h3, l3);
            *(uint2*)(wh + gg * 8) = make_uint2(pk(h0, h1), pk(h2, h3));
            *(uint2*)(wl + gg * 8) = make_uint2(pk(l0, l1), pk(l2, l3));
        }
        ghard[mbase + m] = (float)mi;
    }
    __syncthreads();

    // ---- GEMM2: ctx[m][d] = sum_p W[m][p] * C[p][d]; 4M x 4N grid of 32x64 tiles ----
    {
        const int mrow2 = (wid & 3) * 32;
        const int dcol = (wid >> 2) * 64;
        float dd[16][4];
        #pragma unroll
        for (int i = 0; i < 16; ++i)
            #pragma unroll
            for (int j = 0; j < 4; ++j) dd[i][j] = 0.f;

        const uint32_t wofs[3] = {WH_O, WH_O, WL_O};
        const uint32_t cofs2[3] = {CH_O, CM_O, CH_O};   // C mid == split2-lo of C
        const uint32_t lrow = (uint32_t)(lane & 15);
        const uint32_t lk = (uint32_t)((lane >> 4) * 16);
        const uint32_t btrow = (uint32_t)((lane >> 4) * 8 + (lane & 7));
        const uint32_t btcol = (uint32_t)(((lane >> 3) & 1) * 16);

        #pragma unroll 1
        for (int ps = 0; ps < 3; ++ps) {
            uint32_t ab = smb + wofs[ps] + (mrow2 + lrow) * WP + lk;
            uint32_t bbase = smb + cofs2[ps] + btrow * CPF + dcol * 2 + btcol;
            #pragma unroll
            for (int ks = 0; ks < 4; ++ks) {
                uint32_t a0, a1, a2, a3, a4, a5, a6, a7;
                ldsm4(ab + ks * 32, a0, a1, a2, a3);
                ldsm4(ab + 16 * WP + ks * 32, a4, a5, a6, a7);
                #pragma unroll
                for (int nt = 0; nt < 4; ++nt) {
                    uint32_t r0, r1, r2, r3;
                    ldsm4t(bbase + ks * 16 * CPF + nt * 32, r0, r1, r2, r3);
                    mma16816(dd[nt * 2 + 0], a0, a1, a2, a3, r0, r2);
                    mma16816(dd[nt * 2 + 1], a0, a1, a2, a3, r1, r3);
                    mma16816(dd[8 + nt * 2 + 0], a4, a5, a6, a7, r0, r2);
                    mma16816(dd[8 + nt * 2 + 1], a4, a5, a6, a7, r1, r3);
                }
            }
        }
        // store context
        const int r0 = lane >> 2;
        const int cb = dcol + (lane & 3) * 2;
        #pragma unroll
        for (int mf = 0; mf < 2; ++mf) {
            float* gr0 = gctx + (size_t)(mbase + mrow2 + mf * 16 + r0) * DDIM;
            float* gr1 = gr0 + 8 * DDIM;
            #pragma unroll
            for (int nf = 0; nf < 8; ++nf) {
                float* a = dd[mf * 8 + nf];
                *(float2*)(gr0 + cb + nf * 8) = make_float2(a[0], a[1]);
                *(float2*)(gr1 + cb + nf * 8) = make_float2(a[2], a[3]);
            }
        }
    }
}

extern "C" void kernel_launch(void* const* d_in, const int* in_sizes, int n_in,
                              void* d_out, int out_size)
{
    const float* q = (const float*)d_in[0];
    const float* c = (const float*)d_in[1];
    const int*   mask = (const int*)d_in[2];

    const int Pn = in_sizes[2];              // 64
    const int Dn = in_sizes[1] / Pn;         // 256
    const int B  = in_sizes[0] / Dn;         // 131072

    float* out  = (float*)d_out;
    float* ctx  = out;                           // [B, D]
    float* w    = out + (size_t)B * Dn;          // [B, P]
    float* hard = w + (size_t)B * Pn;            // [B]

    cudaFuncSetAttribute(centroid_hmma2_kernel,
                         cudaFuncAttributeMaxDynamicSharedMemorySize, SMEM_BYTES);
    centroid_hmma2_kernel<<<B / MTILE, NTHREADS, SMEM_BYTES>>>(q, c, mask, ctx, w, hard);
}